// round 10
// baseline (speedup 1.0000x reference)
#include <cuda_runtime.h>
#include <cuda_bf16.h>
#include <cuda_fp16.h>
#include <cstdint>

#define GH 8
#define GW 8
#define RR 64
#define BB 8
#define CIN 128
#define COUT 256
#define NPIX 1024
#define NN 8192           // GEMM N per region (BB*NPIX)
#define KP2 256           // packed K: [gelu(128) | x(128)] fp16
#define EPSV 1e-5f
#define NCH 8             // region pipeline chunks
#define RCH (RR / NCH)    // 8 regions per chunk

// ---------------- scratch (device globals; no runtime allocation) -------------
__device__ __half g_Sh[(size_t)RR * NN * KP2];            // 256 MB
__device__ __half g_Wh[(size_t)RR * COUT * KP2];          // 8 MB
__device__ float g_bias[RR * COUT];

// ---------------- helpers -----------------------------------------------------
__device__ __forceinline__ uint32_t smem_u32(const void* p) {
    uint32_t a;
    asm("{ .reg .u64 t; cvta.to.shared.u64 t, %1; cvt.u32.u64 %0, t; }" : "=r"(a) : "l"(p));
    return a;
}
__device__ __forceinline__ void cpa16(uint32_t dst, const void* src) {
    asm volatile("cp.async.cg.shared.global [%0], [%1], 16;" :: "r"(dst), "l"(src) : "memory");
}
#define LDSM4(d, addr)                                                          \
    asm volatile("ldmatrix.sync.aligned.m8n8.x4.shared.b16 {%0,%1,%2,%3}, [%4];" \
                 : "=r"((d)[0]), "=r"((d)[1]), "=r"((d)[2]), "=r"((d)[3])        \
                 : "r"(addr))
#define MMAH(c, a, b0v, b1v)                                                     \
    asm volatile("mma.sync.aligned.m16n8k16.row.col.f32.f16.f16.f32 "            \
                 "{%0,%1,%2,%3},{%4,%5,%6,%7},{%8,%9},{%0,%1,%2,%3};"            \
                 : "+f"((c)[0]), "+f"((c)[1]), "+f"((c)[2]), "+f"((c)[3])        \
                 : "r"((a)[0]), "r"((a)[1]), "r"((a)[2]), "r"((a)[3]),           \
                   "r"(b0v), "r"(b1v))

// ---------------- kernel 0: fold BN2 into fp16 weights ------------------------
__global__ __launch_bounds__(256) void k_prep(const float* __restrict__ pw_w,
                                              const float* __restrict__ res_w,
                                              const float* __restrict__ g2,
                                              const float* __restrict__ b2,
                                              const float* __restrict__ m2,
                                              const float* __restrict__ v2) {
    int idx = blockIdx.x * 256 + threadIdx.x;      // RR*COUT*256
    int r = idx >> 16;
    int rem = idx & 65535;
    int o = rem >> 8;
    int k = rem & 255;
    int ro = r * COUT + o;
    float rs = rsqrtf(v2[ro] + EPSV);
    float scv = g2[ro] * rs;
    float wv = (k < CIN) ? scv * pw_w[(size_t)ro * CIN + k]
                         : res_w[(size_t)ro * CIN + (k - CIN)];
    g_Wh[(size_t)ro * KP2 + k] = __float2half(wv);
    if (k == 0) g_bias[ro] = b2[ro] - g2[ro] * m2[ro] * rs;
}

// ---------------- kernel 1: dw 3x3 + BN1 + GELU -> S[r][n][k] fp16 ------------
#define CSTR 205   // 6*34 + 1 (odd -> conflict-free channel stride)
__global__ __launch_bounds__(512) void k_dw(const float* __restrict__ x,
                                            const float* __restrict__ dw_w,
                                            const float* __restrict__ g1,
                                            const float* __restrict__ b1,
                                            const float* __restrict__ m1,
                                            const float* __restrict__ v1,
                                            int r_base) {
    extern __shared__ float sx[];  // [128 ch][6 rows][34 cols], stride CSTR
    int bxx = blockIdx.x;
    int chunk = bxx & 7, bb = (bxx >> 3) & 7, r = r_base + (bxx >> 6);
    int gh = r >> 3, gw = r & 7;
    int tid = threadIdx.x;
    int r0 = chunk * 4;

    for (int i = tid; i < 128 * CSTR; i += 512) sx[i] = 0.f;
    __syncthreads();
    for (int i = tid; i < 6 * 128 * 32; i += 512) {
        int rr = i >> 12;
        int c = (i >> 5) & 127;
        int col = i & 31;
        int g = r0 - 1 + rr;
        if (g >= 0 && g < 32)
            sx[c * CSTR + rr * 34 + 1 + col] =
                x[(((size_t)(bb * CIN + c)) * 256 + gh * 32 + g) * 256 + gw * 32 + col];
    }
    __syncthreads();

    int c = tid & 127, ps = tid >> 7;
    int rc = r * CIN + c;
    float w9[9];
    const float* wp = dw_w + (size_t)rc * 9;
#pragma unroll
    for (int i = 0; i < 9; i++) w9[i] = wp[i];
    float rs = rsqrtf(v1[rc] + EPSV);
    float sc = g1[rc] * rs;
    float sh = b1[rc] - g1[rc] * m1[rc] * rs;

    int row = r0 + ps;
    const float* sb = sx + c * CSTR + ps * 34;
    __half* Sp = g_Sh + ((size_t)r * NN + (size_t)bb * NPIX + (size_t)row * 32) * KP2;

#pragma unroll 4
    for (int col = 0; col < 32; col++) {
        float acc = 0.f;
#pragma unroll
        for (int dr = 0; dr < 3; dr++)
#pragma unroll
            for (int dc = 0; dc < 3; dc++)
                acc = fmaf(sb[dr * 34 + col + dc], w9[dr * 3 + dc], acc);
        float yv = fmaf(acc, sc, sh);
        float gv = yv * normcdff(yv);               // exact GELU
        float xv = sb[34 + col + 1];
        __half* o = Sp + (size_t)col * KP2;
        o[c] = __float2half(gv);
        o[128 + c] = __float2half(xv);
    }
}

// ---------------- kernel 2: fp16 1-term warp-MMA GEMM + epilogue --------------
// CTA tile 128m x 256n, 512 threads / 16 warps (warp tile 32x64), K-chunk 64.
// SMEM per stage (halfs): A @0 (128x72), B @9216 (256x72).
#define STG_E 27648
#define STG_B (STG_E * 2)          // 55296 bytes/stage

__global__ __launch_bounds__(512, 1) void k_gemm(float* __restrict__ out, int r_base) {
    extern __shared__ __half smb[];
    uint32_t sbase = smem_u32(smb);
    int tid = threadIdx.x, lane = tid & 31, wid = tid >> 5;
    int wm = wid & 3, wn = wid >> 2;                 // 4x4 warp grid; warp = 32m x 64n
    int m0 = blockIdx.x * 128, n0 = blockIdx.y * 256, r = r_base + blockIdx.z;
    int gh = r >> 3, gw = r & 7;

    const __half* Wp = g_Wh + (size_t)(r * COUT + m0) * KP2;
    const __half* Sp = g_Sh + ((size_t)r * NN + n0) * KP2;

    float acc[2][8][4];
#pragma unroll
    for (int i = 0; i < 2; i++)
#pragma unroll
        for (int j = 0; j < 8; j++)
#pragma unroll
            for (int t = 0; t < 4; t++) acc[i][j][t] = 0.f;

    // cp.async load of one stage: A (128x64) + B (256x64)
    auto load_stage = [&](int s, int kc) {
        uint32_t st = sbase + (uint32_t)s * STG_B;
#pragma unroll
        for (int i = tid; i < 1024; i += 512) {      // A: 128 rows x 8 segs
            int rw = i >> 3, sg = i & 7;
            cpa16(st + 2u * (rw * 72 + sg * 8),
                  Wp + (size_t)rw * KP2 + kc + sg * 8);
        }
#pragma unroll
        for (int i = tid; i < 2048; i += 512) {      // B: 256 rows x 8 segs
            int rw = (i >> 3) & 255, sg = i & 7;
            cpa16(st + 2u * (9216 + rw * 72 + sg * 8),
                  Sp + (size_t)rw * KP2 + kc + sg * 8);
        }
        asm volatile("cp.async.commit_group;" ::: "memory");
    };

    int lrow = lane & 15, lc8 = (lane >> 4) * 8;     // ldmatrix address split
    load_stage(0, 0);

    for (int c = 0; c < 4; c++) {
        if (c < 3) load_stage((c + 1) & 1, (c + 1) * 64);
        if (c < 3) asm volatile("cp.async.wait_group 1;" ::: "memory");
        else       asm volatile("cp.async.wait_group 0;" ::: "memory");
        __syncthreads();

        uint32_t st = sbase + (uint32_t)(c & 1) * STG_B;
        uint32_t aA = st + 2u * ((wm * 32 + lrow) * 72 + lc8);
        uint32_t aB = st + 2u * (9216 + (wn * 64 + lrow) * 72 + lc8);

#pragma unroll
        for (int ks = 0; ks < 4; ks++) {
            uint32_t ko = 2u * (ks * 16);
            uint32_t ah[2][4], b[4][4];
#pragma unroll
            for (int mt = 0; mt < 2; mt++) LDSM4(ah[mt], aA + 2u * (mt * 16 * 72) + ko);
#pragma unroll
            for (int p = 0; p < 4; p++)    LDSM4(b[p], aB + 2u * (p * 16 * 72) + ko);
#pragma unroll
            for (int mt = 0; mt < 2; mt++)
#pragma unroll
                for (int nt = 0; nt < 8; nt++)
                    MMAH(acc[mt][nt], ah[mt], b[nt >> 1][nt & 1], b[nt >> 1][2 + (nt & 1)]);
        }
        __syncthreads();
    }

    // ---- epilogue: bias + scatter to [B, COUT, 256, 256] ----
    int qrow = lane >> 2, qcol = (lane & 3) * 2;
#pragma unroll
    for (int mt = 0; mt < 2; mt++) {
        int mrow = m0 + wm * 32 + mt * 16 + qrow;
        float bi0 = g_bias[r * COUT + mrow];
        float bi1 = g_bias[r * COUT + mrow + 8];
#pragma unroll
        for (int nt = 0; nt < 8; nt++) {
            int nidx = n0 + wn * 64 + nt * 8 + qcol;
            int b2i = nidx >> 10, hw = nidx & 1023;
            int prow = hw >> 5, pcol = hw & 31;
            size_t off0 = (((size_t)(b2i * COUT + mrow) * 256 + gh * 32 + prow) * 256 +
                           gw * 32 + pcol);
            size_t off1 = off0 + (size_t)8 * 65536;          // mrow+8
            float2 v0 = make_float2(acc[mt][nt][0] + bi0, acc[mt][nt][1] + bi0);
            float2 v1 = make_float2(acc[mt][nt][2] + bi1, acc[mt][nt][3] + bi1);
            *(float2*)&out[off0] = v0;
            *(float2*)&out[off1] = v1;
        }
    }
}

// ---------------- launch: 2-stream region pipeline ----------------------------
extern "C" void kernel_launch(void* const* d_in, const int* in_sizes, int n_in,
                              void* d_out, int out_size) {
    const float* x     = (const float*)d_in[0];
    const float* dw_w  = (const float*)d_in[1];
    const float* bn1_g = (const float*)d_in[2];
    const float* bn1_b = (const float*)d_in[3];
    const float* bn1_m = (const float*)d_in[4];
    const float* bn1_v = (const float*)d_in[5];
    const float* pw_w  = (const float*)d_in[6];
    const float* bn2_g = (const float*)d_in[7];
    const float* bn2_b = (const float*)d_in[8];
    const float* bn2_m = (const float*)d_in[9];
    const float* bn2_v = (const float*)d_in[10];
    const float* res_w = (const float*)d_in[11];
    float* out = (float*)d_out;

    // one-time host-object setup (first call is eager/uncaptured)
    static cudaStream_t sDw = nullptr, sGm = nullptr;
    static cudaEvent_t evRoot, evGm, evDw[NCH];
    if (!sDw) {
        cudaStreamCreateWithFlags(&sDw, cudaStreamNonBlocking);
        cudaStreamCreateWithFlags(&sGm, cudaStreamNonBlocking);
        cudaEventCreateWithFlags(&evRoot, cudaEventDisableTiming);
        cudaEventCreateWithFlags(&evGm, cudaEventDisableTiming);
        for (int c = 0; c < NCH; c++)
            cudaEventCreateWithFlags(&evDw[c], cudaEventDisableTiming);
        cudaFuncSetAttribute(k_gemm, cudaFuncAttributeMaxDynamicSharedMemorySize,
                             2 * STG_B);
        cudaFuncSetAttribute(k_dw, cudaFuncAttributeMaxDynamicSharedMemorySize,
                             128 * CSTR * 4);
    }

    // fork both worker streams off the capture-origin (default) stream
    cudaEventRecord(evRoot, 0);
    cudaStreamWaitEvent(sDw, evRoot, 0);
    cudaStreamWaitEvent(sGm, evRoot, 0);

    k_prep<<<(RR * COUT * 256) / 256, 256, 0, sGm>>>(pw_w, res_w, bn2_g, bn2_b,
                                                     bn2_m, bn2_v);

    for (int c = 0; c < NCH; c++) {
        k_dw<<<RCH * BB * 8, 512, 128 * CSTR * 4, sDw>>>(x, dw_w, bn1_g, bn1_b,
                                                         bn1_m, bn1_v, c * RCH);
        cudaEventRecord(evDw[c], sDw);
        cudaStreamWaitEvent(sGm, evDw[c], 0);
        dim3 grid(COUT / 128, NN / 256, RCH);
        k_gemm<<<grid, 512, 2 * STG_B, sGm>>>(out, c * RCH);
    }

    // join back to the origin stream (sDw joins transitively via evDw[NCH-1])
    cudaEventRecord(evGm, sGm);
    cudaStreamWaitEvent(0, evGm, 0);
}

// round 11
// speedup vs baseline: 1.0592x; 1.0592x over previous
#include <cuda_runtime.h>
#include <cuda_bf16.h>
#include <cuda_fp16.h>
#include <cstdint>

#define GH 8
#define GW 8
#define RR 64
#define BB 8
#define CIN 128
#define COUT 256
#define NPIX 1024
#define NN 8192           // GEMM N per region (BB*NPIX)
#define KP2 256           // packed K: [gelu(128) | x(128)] fp16
#define EPSV 1e-5f

// ---------------- scratch (device globals; no runtime allocation) -------------
__device__ __half g_Sh[(size_t)RR * NN * KP2];            // 256 MB
__device__ __half g_Wh[(size_t)RR * COUT * KP2];          // 8 MB
__device__ float g_bias[RR * COUT];

// ---------------- helpers -----------------------------------------------------
__device__ __forceinline__ uint32_t smem_u32(const void* p) {
    uint32_t a;
    asm("{ .reg .u64 t; cvta.to.shared.u64 t, %1; cvt.u32.u64 %0, t; }" : "=r"(a) : "l"(p));
    return a;
}
__device__ __forceinline__ void cpa16(uint32_t dst, const void* src) {
    asm volatile("cp.async.cg.shared.global [%0], [%1], 16;" :: "r"(dst), "l"(src) : "memory");
}
#define LDSM4(d, addr)                                                          \
    asm volatile("ldmatrix.sync.aligned.m8n8.x4.shared.b16 {%0,%1,%2,%3}, [%4];" \
                 : "=r"((d)[0]), "=r"((d)[1]), "=r"((d)[2]), "=r"((d)[3])        \
                 : "r"(addr))
#define MMAH(c, a, b0v, b1v)                                                     \
    asm volatile("mma.sync.aligned.m16n8k16.row.col.f32.f16.f16.f32 "            \
                 "{%0,%1,%2,%3},{%4,%5,%6,%7},{%8,%9},{%0,%1,%2,%3};"            \
                 : "+f"((c)[0]), "+f"((c)[1]), "+f"((c)[2]), "+f"((c)[3])        \
                 : "r"((a)[0]), "r"((a)[1]), "r"((a)[2]), "r"((a)[3]),           \
                   "r"(b0v), "r"(b1v))

// ---------------- kernel 0: fold BN2 into fp16 weights ------------------------
__global__ __launch_bounds__(256) void k_prep(const float* __restrict__ pw_w,
                                              const float* __restrict__ res_w,
                                              const float* __restrict__ g2,
                                              const float* __restrict__ b2,
                                              const float* __restrict__ m2,
                                              const float* __restrict__ v2) {
    int idx = blockIdx.x * 256 + threadIdx.x;      // RR*COUT*256
    int r = idx >> 16;
    int rem = idx & 65535;
    int o = rem >> 8;
    int k = rem & 255;
    int ro = r * COUT + o;
    float rs = rsqrtf(v2[ro] + EPSV);
    float scv = g2[ro] * rs;
    float wv = (k < CIN) ? scv * pw_w[(size_t)ro * CIN + k]
                         : res_w[(size_t)ro * CIN + (k - CIN)];
    g_Wh[(size_t)ro * KP2 + k] = __float2half(wv);
    if (k == 0) g_bias[ro] = b2[ro] - g2[ro] * m2[ro] * rs;
}

// ---------------- kernel 1: dw 3x3 + BN1 + GELU -> S[r][n][k] fp16 ------------
// 256 threads / 64 channels per block (4 blocks/SM), 4-row chunks, sliding-window
// conv (3 LDS + 9 FMA per column instead of 9 LDS + 9 FMA).
#define CSTR 205   // 6*34 + 1 (odd -> conflict-free channel stride)
#define DW_SMEM (64 * CSTR * 4)
__global__ __launch_bounds__(256, 4) void k_dw(const float* __restrict__ x,
                                               const float* __restrict__ dw_w,
                                               const float* __restrict__ g1,
                                               const float* __restrict__ b1,
                                               const float* __restrict__ m1,
                                               const float* __restrict__ v1) {
    extern __shared__ float sx[];  // [64 ch][6 rows][34 cols], stride CSTR
    int bxx = blockIdx.x;          // 8192 = r(64) x bb(8) x chunk(8) x cg(2)
    int cg = bxx & 1, chunk = (bxx >> 1) & 7, bb = (bxx >> 4) & 7, r = bxx >> 7;
    int gh = r >> 3, gw = r & 7;
    int tid = threadIdx.x;
    int r0 = chunk * 4;

    for (int i = tid; i < 64 * CSTR; i += 256) sx[i] = 0.f;
    __syncthreads();
    // load 6 input rows x 32 cols x 64 ch (zero-padded at tile boundary)
    for (int i = tid; i < 6 * 64 * 32; i += 256) {
        int rr = i >> 11;
        int c = (i >> 5) & 63;
        int col = i & 31;
        int g = r0 - 1 + rr;
        if (g >= 0 && g < 32)
            sx[c * CSTR + rr * 34 + 1 + col] =
                x[(((size_t)(bb * CIN + cg * 64 + c)) * 256 + gh * 32 + g) * 256 +
                  gw * 32 + col];
    }
    __syncthreads();

    int c = tid & 63, ps = tid >> 6;               // ps in 0..3 (row within chunk)
    int ch = cg * 64 + c;
    int rc = r * CIN + ch;
    float w9[9];
    const float* wp = dw_w + (size_t)rc * 9;
#pragma unroll
    for (int i = 0; i < 9; i++) w9[i] = wp[i];
    float rs = rsqrtf(v1[rc] + EPSV);
    float sc = g1[rc] * rs;
    float sh = b1[rc] - g1[rc] * m1[rc] * rs;

    int row = r0 + ps;
    const float* sb = sx + c * CSTR + ps * 34;     // rows row-1..row+1 at sb[0/34/68]
    __half* o = g_Sh + ((size_t)r * NN + (size_t)bb * NPIX + (size_t)row * 32) * KP2 + ch;

    // sliding window: P[col] = q0(col) + q1(col+1) + q2(col+2),
    // q_dc(ci) = sum_dr w[dr*3+dc] * v[dr][ci]. A=P[ci-2], B=P[ci-1], C=P[ci].
    float A = 0.f, B = 0.f, cPrev = 0.f;
#pragma unroll
    for (int ci = 0; ci < 34; ci++) {
        float v0 = sb[ci], v1 = sb[34 + ci], v2 = sb[68 + ci];
        // C = q0(ci)
        float C = fmaf(w9[6], v2, fmaf(w9[3], v1, w9[0] * v0));
        // B += q1(ci)
        B = fmaf(w9[7], v2, fmaf(w9[4], v1, fmaf(w9[1], v0, B)));
        // A += q2(ci)
        A = fmaf(w9[8], v2, fmaf(w9[5], v1, fmaf(w9[2], v0, A)));
        if (ci >= 2) {
            float yv = fmaf(A, sc, sh);
            float gv = yv * normcdff(yv);          // exact GELU
            o[0]   = __float2half(gv);
            o[128] = __float2half(cPrev);          // raw x = v[1][ci-1]
            o += KP2;
        }
        A = B; B = C;
        cPrev = v1;
    }
}

// ---------------- kernel 2: fp16 1-term warp-MMA GEMM + epilogue --------------
// CTA tile 128m x 256n, 512 threads / 16 warps (warp tile 32x64), K-chunk 64.
// SMEM per stage (halfs): A @0 (128x72), B @9216 (256x72).
#define STG_E 27648
#define STG_B (STG_E * 2)          // 55296 bytes/stage

__global__ __launch_bounds__(512, 1) void k_gemm(float* __restrict__ out) {
    extern __shared__ __half smb[];
    uint32_t sbase = smem_u32(smb);
    int tid = threadIdx.x, lane = tid & 31, wid = tid >> 5;
    int wm = wid & 3, wn = wid >> 2;                 // 4x4 warp grid; warp = 32m x 64n
    int m0 = blockIdx.x * 128, n0 = blockIdx.y * 256, r = blockIdx.z;
    int gh = r >> 3, gw = r & 7;

    const __half* Wp = g_Wh + (size_t)(r * COUT + m0) * KP2;
    const __half* Sp = g_Sh + ((size_t)r * NN + n0) * KP2;

    float acc[2][8][4];
#pragma unroll
    for (int i = 0; i < 2; i++)
#pragma unroll
        for (int j = 0; j < 8; j++)
#pragma unroll
            for (int t = 0; t < 4; t++) acc[i][j][t] = 0.f;

    // cp.async load of one stage: A (128x64) + B (256x64)
    auto load_stage = [&](int s, int kc) {
        uint32_t st = sbase + (uint32_t)s * STG_B;
#pragma unroll
        for (int i = tid; i < 1024; i += 512) {      // A: 128 rows x 8 segs
            int rw = i >> 3, sg = i & 7;
            cpa16(st + 2u * (rw * 72 + sg * 8),
                  Wp + (size_t)rw * KP2 + kc + sg * 8);
        }
#pragma unroll
        for (int i = tid; i < 2048; i += 512) {      // B: 256 rows x 8 segs
            int rw = (i >> 3) & 255, sg = i & 7;
            cpa16(st + 2u * (9216 + rw * 72 + sg * 8),
                  Sp + (size_t)rw * KP2 + kc + sg * 8);
        }
        asm volatile("cp.async.commit_group;" ::: "memory");
    };

    int lrow = lane & 15, lc8 = (lane >> 4) * 8;     // ldmatrix address split
    load_stage(0, 0);

    for (int c = 0; c < 4; c++) {
        if (c < 3) load_stage((c + 1) & 1, (c + 1) * 64);
        if (c < 3) asm volatile("cp.async.wait_group 1;" ::: "memory");
        else       asm volatile("cp.async.wait_group 0;" ::: "memory");
        __syncthreads();

        uint32_t st = sbase + (uint32_t)(c & 1) * STG_B;
        uint32_t aA = st + 2u * ((wm * 32 + lrow) * 72 + lc8);
        uint32_t aB = st + 2u * (9216 + (wn * 64 + lrow) * 72 + lc8);

#pragma unroll
        for (int ks = 0; ks < 4; ks++) {
            uint32_t ko = 2u * (ks * 16);
            uint32_t ah[2][4], b[4][4];
#pragma unroll
            for (int mt = 0; mt < 2; mt++) LDSM4(ah[mt], aA + 2u * (mt * 16 * 72) + ko);
#pragma unroll
            for (int p = 0; p < 4; p++)    LDSM4(b[p], aB + 2u * (p * 16 * 72) + ko);
#pragma unroll
            for (int mt = 0; mt < 2; mt++)
#pragma unroll
                for (int nt = 0; nt < 8; nt++)
                    MMAH(acc[mt][nt], ah[mt], b[nt >> 1][nt & 1], b[nt >> 1][2 + (nt & 1)]);
        }
        __syncthreads();
    }

    // ---- epilogue: bias + scatter to [B, COUT, 256, 256] ----
    int qrow = lane >> 2, qcol = (lane & 3) * 2;
#pragma unroll
    for (int mt = 0; mt < 2; mt++) {
        int mrow = m0 + wm * 32 + mt * 16 + qrow;
        float bi0 = g_bias[r * COUT + mrow];
        float bi1 = g_bias[r * COUT + mrow + 8];
#pragma unroll
        for (int nt = 0; nt < 8; nt++) {
            int nidx = n0 + wn * 64 + nt * 8 + qcol;
            int b2i = nidx >> 10, hw = nidx & 1023;
            int prow = hw >> 5, pcol = hw & 31;
            size_t off0 = (((size_t)(b2i * COUT + mrow) * 256 + gh * 32 + prow) * 256 +
                           gw * 32 + pcol);
            size_t off1 = off0 + (size_t)8 * 65536;          // mrow+8
            float2 v0 = make_float2(acc[mt][nt][0] + bi0, acc[mt][nt][1] + bi0);
            float2 v1 = make_float2(acc[mt][nt][2] + bi1, acc[mt][nt][3] + bi1);
            *(float2*)&out[off0] = v0;
            *(float2*)&out[off1] = v1;
        }
    }
}

// ---------------- launch (single stream) --------------------------------------
extern "C" void kernel_launch(void* const* d_in, const int* in_sizes, int n_in,
                              void* d_out, int out_size) {
    const float* x     = (const float*)d_in[0];
    const float* dw_w  = (const float*)d_in[1];
    const float* bn1_g = (const float*)d_in[2];
    const float* bn1_b = (const float*)d_in[3];
    const float* bn1_m = (const float*)d_in[4];
    const float* bn1_v = (const float*)d_in[5];
    const float* pw_w  = (const float*)d_in[6];
    const float* bn2_g = (const float*)d_in[7];
    const float* bn2_b = (const float*)d_in[8];
    const float* bn2_m = (const float*)d_in[9];
    const float* bn2_v = (const float*)d_in[10];
    const float* res_w = (const float*)d_in[11];
    float* out = (float*)d_out;

    cudaFuncSetAttribute(k_gemm, cudaFuncAttributeMaxDynamicSharedMemorySize,
                         2 * STG_B);
    cudaFuncSetAttribute(k_dw, cudaFuncAttributeMaxDynamicSharedMemorySize,
                         DW_SMEM);

    k_prep<<<(RR * COUT * 256) / 256, 256>>>(pw_w, res_w, bn2_g, bn2_b, bn2_m, bn2_v);
    k_dw<<<RR * BB * 8 * 2, 256, DW_SMEM>>>(x, dw_w, bn1_g, bn1_b, bn1_m, bn1_v);
    // x = m-block fastest: the 2 CTAs sharing one B tile run adjacently (L2 reuse)
    dim3 grid(COUT / 128, NN / 256, RR);
    k_gemm<<<grid, 512, 2 * STG_B>>>(out);
}